// round 14
// baseline (speedup 1.0000x reference)
#include <cuda_runtime.h>
#include <cuda_bf16.h>
#include <math.h>

#define Dd 256
#define Bb 32
#define Ff 512
#define Tt 32

typedef unsigned long long ull;

// ---------------- scratch -----------------------------------------------------
__device__ float g_pe[Ff * Dd];
__device__ float g_arg[Bb * Ff * Dd];          // base + accumulated s@Ws^T
__device__ ull   g_WhP[128 * 256];
__device__ ull   g_wcombP[384 * 1024];         // [jp][gcol]
__device__ ull   g_WgP[256 * 256];
// HMMA B-fragment packs: [ks][ntile][lane] uint4 = {hi k0 pair, hi k0+8 pair, lo..., lo...}
__device__ uint4 g_WeF[16384];
__device__ uint4 g_WsF[16384];
__device__ uint4 g_WfF[16384];
__device__ uint4 g_WqF[16384];
__device__ ull   g_XTP[384 * 32];              // [jp][b] packed input pairs for gates
__device__ float g_h[Bb * Dd], g_cell[Bb * Dd], g_hw[Bb * Dd];
__device__ float g_cpart[256 * 256], g_cppart[256 * 256];

__device__ __forceinline__ float sigm(float x) { return 1.0f / (1.0f + expf(-x)); }
__device__ __forceinline__ ull pack2(float a, float b) {
    ull r; asm("mov.b64 %0, {%1, %2};" : "=l"(r) : "f"(a), "f"(b)); return r;
}
__device__ __forceinline__ float red2(ull a) {
    return __uint_as_float((unsigned)a) + __uint_as_float((unsigned)(a >> 32));
}
__device__ __forceinline__ unsigned pkbf(float a, float b) {
    __nv_bfloat16 ha = __float2bfloat16(a), hb = __float2bfloat16(b);
    return (unsigned)__bfloat16_as_ushort(ha) | ((unsigned)__bfloat16_as_ushort(hb) << 16);
}

#define MMA(d, a, b0, b1) \
    asm("mma.sync.aligned.m16n8k16.row.col.f32.bf16.bf16.f32 " \
        "{%0,%1,%2,%3},{%4,%5,%6,%7},{%8,%9},{%0,%1,%2,%3};" \
        : "+f"((d)[0]), "+f"((d)[1]), "+f"((d)[2]), "+f"((d)[3]) \
        : "r"((a)[0]), "r"((a)[1]), "r"((a)[2]), "r"((a)[3]), "r"(b0), "r"(b1))

// ---------------- mega-setup ---------------------------------------------------
__global__ void setup_a(const float* __restrict__ w_f, const float* __restrict__ w_q,
                        const float* __restrict__ w_h, const float* __restrict__ w_ih,
                        const float* __restrict__ w_hh, const float* __restrict__ w_g,
                        const float* __restrict__ w_e, const float* __restrict__ w_s,
                        const int* __restrict__ ids, const float* __restrict__ emb) {
    int bb = blockIdx.x, tid = threadIdx.x;
    if (bb < 512) {
        int idx = bb * 256 + tid;
        int pos = idx >> 8, d = idx & 255;
        float expo = (float)(d & ~1) / (float)Dd;
        float ang = (float)pos / powf(10000.0f, expo);
        double a = (double)ang;
        g_pe[idx] = (d & 1) ? (float)cos(a) : (float)sin(a);
    } else if (bb < 640) {
        int idx = (bb - 512) * 256 + tid;
        int k = idx >> 8, o = idx & 255;
        g_WhP[idx] = pack2(w_h[o * 256 + 2 * k], w_h[o * 256 + 2 * k + 1]);
    } else if (bb < 2176) {
        int idx = (bb - 640) * 256 + tid;
        int jp = idx >> 10, gcol = idx & 1023;
        float a, b;
        if (jp < 256) { a = w_ih[gcol * 512 + 2 * jp]; b = w_ih[gcol * 512 + 2 * jp + 1]; }
        else { int j2 = jp - 256; a = w_hh[gcol * 256 + 2 * j2]; b = w_hh[gcol * 256 + 2 * j2 + 1]; }
        g_wcombP[idx] = pack2(a, b);
    } else if (bb < 2432) {
        int idx = (bb - 2176) * 256 + tid;
        int jp = idx >> 8, o = idx & 255;
        g_WgP[idx] = pack2(w_g[o * 512 + 2 * jp], w_g[o * 512 + 2 * jp + 1]);
    } else if (bb < 2688) {
        int idx = (bb - 2432) * 256 + tid;          // 0..65535
        int sel = idx >> 14;
        const float* W = (sel == 0) ? w_e : (sel == 1) ? w_s : (sel == 2) ? w_f : w_q;
        uint4* dst = (sel == 0) ? g_WeF : (sel == 1) ? g_WsF : (sel == 2) ? g_WfF : g_WqF;
        int e = idx & 16383;
        int ks = e >> 10, ntg = (e >> 5) & 31, ln = e & 31;
        int n = ntg * 8 + (ln >> 2);
        int k0 = ks * 16 + (ln & 3) * 2;
        float w00 = W[n * 256 + k0],     w01 = W[n * 256 + k0 + 1];
        float w80 = W[n * 256 + k0 + 8], w81 = W[n * 256 + k0 + 9];
        __nv_bfloat16 h00 = __float2bfloat16(w00), h01 = __float2bfloat16(w01);
        __nv_bfloat16 h80 = __float2bfloat16(w80), h81 = __float2bfloat16(w81);
        uint4 v;
        v.x = (unsigned)__bfloat16_as_ushort(h00) | ((unsigned)__bfloat16_as_ushort(h01) << 16);
        v.y = (unsigned)__bfloat16_as_ushort(h80) | ((unsigned)__bfloat16_as_ushort(h81) << 16);
        v.z = pkbf(w00 - __bfloat162float(h00), w01 - __bfloat162float(h01));
        v.w = pkbf(w80 - __bfloat162float(h80), w81 - __bfloat162float(h81));
        dst[e] = v;
    } else if (bb < 2752) {
        int idx = (bb - 2688) * 256 + tid;          // 16384
        if (idx < 8192) g_h[idx] = 0.0f; else g_cell[idx - 8192] = 0.0f;
    } else {
        int idx = (bb - 2752) * 256 + tid;          // 12288 = jp*32 + b
        int jp = idx >> 5, b = idx & 31;
        ull v = 0ULL;
        if (jp < 128) {
            int row = ids[b * Tt] * 256;
            v = pack2(emb[row + 2 * jp], emb[row + 2 * jp + 1]);
        }
        g_XTP[idx] = v;
    }
}

// ---------------- HMMA split-bf16 GEMM core ------------------------------------
__device__ __forceinline__ void gemm_mma(float acc[2][4][4],
                                         const __nv_bfloat16* Xh, const __nv_bfloat16* Xl,
                                         const uint4* __restrict__ WF,
                                         int wm, int wn, int lane, bool zero) {
    int g = lane >> 2, tq = lane & 3;
    if (zero) {
#pragma unroll
        for (int mt = 0; mt < 2; mt++)
#pragma unroll
            for (int nt = 0; nt < 4; nt++)
#pragma unroll
                for (int i = 0; i < 4; i++) acc[mt][nt][i] = 0.0f;
    }
#pragma unroll 2
    for (int ks = 0; ks < 16; ks++) {
        uint4 bf[4];
#pragma unroll
        for (int nt = 0; nt < 4; nt++)
            bf[nt] = WF[((ks * 32 + wn * 4 + nt) * 32) + lane];
        unsigned ah[2][4], al[2][4];
        int k0 = ks * 16 + tq * 2;
#pragma unroll
        for (int mt = 0; mt < 2; mt++) {
            int r0 = wm * 32 + mt * 16 + g;
            ah[mt][0] = *(const unsigned*)(Xh + r0 * 264 + k0);
            ah[mt][1] = *(const unsigned*)(Xh + (r0 + 8) * 264 + k0);
            ah[mt][2] = *(const unsigned*)(Xh + r0 * 264 + k0 + 8);
            ah[mt][3] = *(const unsigned*)(Xh + (r0 + 8) * 264 + k0 + 8);
            al[mt][0] = *(const unsigned*)(Xl + r0 * 264 + k0);
            al[mt][1] = *(const unsigned*)(Xl + (r0 + 8) * 264 + k0);
            al[mt][2] = *(const unsigned*)(Xl + r0 * 264 + k0 + 8);
            al[mt][3] = *(const unsigned*)(Xl + (r0 + 8) * 264 + k0 + 8);
        }
#pragma unroll
        for (int nt = 0; nt < 4; nt++)
#pragma unroll
            for (int mt = 0; mt < 2; mt++) {
                MMA(acc[mt][nt], ah[mt], bf[nt].x, bf[nt].y);
                MMA(acc[mt][nt], ah[mt], bf[nt].z, bf[nt].w);
                MMA(acc[mt][nt], al[mt], bf[nt].x, bf[nt].y);
            }
    }
}

// smem byte offsets (dynamic smem, attn/base)
#define XH_OFF 0
#define XL_OFF 33792
#define RS_OFF 67584
#define RT_OFF 69632
#define PC_OFF 69888
#define PQ_OFF 71936
#define ATT_SMEM 73984

// ---------------- base: arg = f @ Wf^T + pe @ Wq^T (HMMA) ----------------------
__global__ void __launch_bounds__(512, 1) base_kernel(const float* __restrict__ f) {
    extern __shared__ __align__(16) unsigned char smem[];
    __nv_bfloat16* Xh = (__nv_bfloat16*)(smem + XH_OFF);
    __nv_bfloat16* Xl = (__nv_bfloat16*)(smem + XL_OFF);
    int tid = threadIdx.x;
    int tile = blockIdx.x;
    int b = tile >> 3, f0 = (tile & 7) * 64;
    size_t rb = ((size_t)b * Ff + f0) * Dd;
    int lane = tid & 31, wid = tid >> 5;
    int wm = wid & 1, wn = wid >> 1;
    int g = lane >> 2, tq = lane & 3;
    float acc[2][4][4];

    {
        int c = tid & 255, hf = tid >> 8;
#pragma unroll 4
        for (int r = 0; r < 32; r++) {
            int row = hf * 32 + r;
            float x = g_pe[(size_t)(f0 + row) * 256 + c];
            __nv_bfloat16 h = __float2bfloat16(x);
            Xh[row * 264 + c] = h;
            Xl[row * 264 + c] = __float2bfloat16(x - __bfloat162float(h));
        }
    }
    __syncthreads();
    gemm_mma(acc, Xh, Xl, g_WqF, wm, wn, lane, true);
    __syncthreads();

    {
        int c = tid & 255, hf = tid >> 8;
#pragma unroll 4
        for (int r = 0; r < 32; r++) {
            int row = hf * 32 + r;
            float x = f[rb + (size_t)row * 256 + c];
            __nv_bfloat16 h = __float2bfloat16(x);
            Xh[row * 264 + c] = h;
            Xl[row * 264 + c] = __float2bfloat16(x - __bfloat162float(h));
        }
    }
    __syncthreads();
    gemm_mma(acc, Xh, Xl, g_WfF, wm, wn, lane, false);

#pragma unroll
    for (int mt = 0; mt < 2; mt++)
#pragma unroll
        for (int nt = 0; nt < 4; nt++) {
            int row = wm * 32 + mt * 16 + g;
            int col = wn * 32 + nt * 8 + tq * 2;
            *(float2*)(g_arg + rb + (size_t)row * 256 + col) =
                make_float2(acc[mt][nt][0], acc[mt][nt][1]);
            *(float2*)(g_arg + rb + (size_t)(row + 8) * 256 + col) =
                make_float2(acc[mt][nt][2], acc[mt][nt][3]);
        }
}

// ---------------- gates + cell/h (grid 32 d-sliced, 256 thr) -------------------
#define GSMEM (98304 + 4096)
__global__ void gates_kernel() {
    extern __shared__ __align__(16) unsigned char gsmem[];
    ull* Xs = (ull*)gsmem;                       // [384][32]
    float* gsm = (float*)(gsmem + 98304);        // [32 gcol][32 b]
    int tid = threadIdx.x, bj = blockIdx.x;
    for (int i = tid; i < 12288; i += 256) Xs[i] = g_XTP[i];
    __syncthreads();

    int w = tid >> 5, lane = tid & 31;           // lane = b
    int gg = w >> 1, dbase = (w & 1) * 4;
    const ull* wp = g_wcombP + gg * 256 + 8 * bj + dbase;
    ull acc[4] = {0ULL, 0ULL, 0ULL, 0ULL};
#pragma unroll 4
    for (int jp = 0; jp < 384; jp++) {
        ull x = Xs[jp * 32 + lane];
        ulonglong2 w01 = *(const ulonglong2*)(wp + jp * 1024);
        ulonglong2 w23 = *(const ulonglong2*)(wp + jp * 1024 + 2);
        asm("fma.rn.f32x2 %0,%1,%2,%0;" : "+l"(acc[0]) : "l"(x), "l"(w01.x));
        asm("fma.rn.f32x2 %0,%1,%2,%0;" : "+l"(acc[1]) : "l"(x), "l"(w01.y));
        asm("fma.rn.f32x2 %0,%1,%2,%0;" : "+l"(acc[2]) : "l"(x), "l"(w23.x));
        asm("fma.rn.f32x2 %0,%1,%2,%0;" : "+l"(acc[3]) : "l"(x), "l"(w23.y));
    }
#pragma unroll
    for (int i = 0; i < 4; i++)
        gsm[(gg * 8 + dbase + i) * 32 + lane] = red2(acc[i]);
    __syncthreads();

    int b = tid & 31, dd = tid >> 5;
    int d = 8 * bj + dd;
    float gi = gsm[(0 * 8 + dd) * 32 + b];
    float gf = gsm[(1 * 8 + dd) * 32 + b];
    float gv = gsm[(2 * 8 + dd) * 32 + b];
    float go = gsm[(3 * 8 + dd) * 32 + b];
    float c  = sigm(gf) * g_cell[b * 256 + d] + sigm(gi) * tanhf(gv);
    float hn = sigm(go) * tanhf(c);
    g_cell[b * 256 + d] = c;
    g_h[b * 256 + d] = hn;
}

// ---------------- hw = h @ Wh^T (grid 32, 256 thr) ----------------------------
__global__ void hw_kernel() {
    int b = blockIdx.x, tid = threadIdx.x;
    __shared__ __align__(16) float hb[256];
    hb[tid] = g_h[b * 256 + tid];
    __syncthreads();
    ull a2 = 0ULL;
#pragma unroll 8
    for (int jp = 0; jp < 128; jp++) {
        ull x = *(const ull*)(hb + 2 * jp);
        asm("fma.rn.f32x2 %0,%1,%2,%0;" : "+l"(a2) : "l"(x), "l"(g_WhP[jp * 256 + tid]));
    }
    g_hw[b * 256 + tid] = red2(a2);
}

// ---------------- HMMA attention step (grid 256, 512 thr) ---------------------
__global__ void __launch_bounds__(512, 1) attn_kernel(const float* __restrict__ f) {
    extern __shared__ __align__(16) unsigned char smem[];
    __nv_bfloat16* Xh = (__nv_bfloat16*)(smem + XH_OFF);
    __nv_bfloat16* Xl = (__nv_bfloat16*)(smem + XL_OFF);
    float* rs = (float*)(smem + RS_OFF);
    float* rt = (float*)(smem + RT_OFF);
    float* pc = (float*)(smem + PC_OFF);
    float* pq = (float*)(smem + PQ_OFF);
    int tid = threadIdx.x;
    int tile = blockIdx.x;
    int b = tile >> 3, f0 = (tile & 7) * 64;
    size_t rb = ((size_t)b * Ff + f0) * Dd;

    // phase 1: X = tanh(hw + arg) -> bf16 hi/lo planes
    {
        int c = tid & 255, hf = tid >> 8;
        float hwv = g_hw[b * Dd + c];
#pragma unroll 4
        for (int r = 0; r < 32; r++) {
            int row = hf * 32 + r;
            float x = tanhf(hwv + g_arg[rb + (size_t)row * 256 + c]);
            __nv_bfloat16 h = __float2bfloat16(x);
            Xh[row * 264 + c] = h;
            Xl[row * 264 + c] = __float2bfloat16(x - __bfloat162float(h));
        }
    }
    __syncthreads();

    int lane = tid & 31, wid = tid >> 5;
    int wm = wid & 1, wn = wid >> 1;
    int g = lane >> 2, tq = lane & 3;

    float acc[2][4][4];
    gemm_mma(acc, Xh, Xl, g_WeF, wm, wn, lane, true);

    // softmax (tanh-bounded energies; no max pass)
    {
        float p0[2], p1[2];
#pragma unroll
        for (int mt = 0; mt < 2; mt++) {
            p0[mt] = 0.0f; p1[mt] = 0.0f;
#pragma unroll
            for (int nt = 0; nt < 4; nt++) {
                acc[mt][nt][0] = __expf(acc[mt][nt][0]);
                acc[mt][nt][1] = __expf(acc[mt][nt][1]);
                acc[mt][nt][2] = __expf(acc[mt][nt][2]);
                acc[mt][nt][3] = __expf(acc[mt][nt][3]);
                p0[mt] += acc[mt][nt][0] + acc[mt][nt][1];
                p1[mt] += acc[mt][nt][2] + acc[mt][nt][3];
            }
#pragma unroll
            for (int o = 1; o <= 2; o <<= 1) {
                p0[mt] += __shfl_xor_sync(0xffffffffu, p0[mt], o);
                p1[mt] += __shfl_xor_sync(0xffffffffu, p1[mt], o);
            }
        }
        if (tq == 0) {
#pragma unroll
            for (int mt = 0; mt < 2; mt++) {
                rs[wn * 64 + wm * 32 + mt * 16 + g] = p0[mt];
                rs[wn * 64 + wm * 32 + mt * 16 + g + 8] = p1[mt];
            }
        }
        __syncthreads();
        if (tid < 64) {
            float s = 0.0f;
#pragma unroll
            for (int w = 0; w < 8; w++) s += rs[w * 64 + tid];
            rt[tid] = 1.0f / s;
        }
        __syncthreads();
#pragma unroll
        for (int mt = 0; mt < 2; mt++) {
            float i0 = rt[wm * 32 + mt * 16 + g];
            float i1 = rt[wm * 32 + mt * 16 + g + 8];
#pragma unroll
            for (int nt = 0; nt < 4; nt++) {
                float a0 = acc[mt][nt][0] * i0, a1 = acc[mt][nt][1] * i0;
                float a2 = acc[mt][nt][2] * i1, a3 = acc[mt][nt][3] * i1;
                int row = wm * 32 + mt * 16 + g;
                int col = wn * 32 + nt * 8 + tq * 2;
                __nv_bfloat16 h0 = __float2bfloat16(a0), h1 = __float2bfloat16(a1);
                __nv_bfloat16 h2 = __float2bfloat16(a2), h3 = __float2bfloat16(a3);
                *(unsigned*)(Xh + row * 264 + col) =
                    (unsigned)__bfloat16_as_ushort(h0) | ((unsigned)__bfloat16_as_ushort(h1) << 16);
                *(unsigned*)(Xl + row * 264 + col) =
                    pkbf(a0 - __bfloat162float(h0), a1 - __bfloat162float(h1));
                *(unsigned*)(Xh + (row + 8) * 264 + col) =
                    (unsigned)__bfloat16_as_ushort(h2) | ((unsigned)__bfloat16_as_ushort(h3) << 16);
                *(unsigned*)(Xl + (row + 8) * 264 + col) =
                    pkbf(a2 - __bfloat162float(h2), a3 - __bfloat162float(h3));
            }
        }
    }
    __syncthreads();

    // c / cp partial reductions
    {
        int c = tid & 255, hf = tid >> 8;
        float ca = 0.0f, qa = 0.0f;
        const float* fp = f + rb + (size_t)(hf * 32) * 256 + c;
        const float* pp = g_pe + (size_t)(f0 + hf * 32) * 256 + c;
#pragma unroll 4
        for (int r = 0; r < 32; r++) {
            int row = hf * 32 + r;
            float a = __bfloat162float(Xh[row * 264 + c]) + __bfloat162float(Xl[row * 264 + c]);
            ca += a * fp[r * 256];
            qa += a * pp[r * 256];
        }
        pc[hf * 256 + c] = ca;
        pq[hf * 256 + c] = qa;
    }
    __syncthreads();
    if (tid < 256) {
        float c2 = pc[tid] + pc[256 + tid];
        float q2 = pq[tid] + pq[256 + tid];
        g_cpart[tile * 256 + tid] = c2;
        g_cppart[tile * 256 + tid] = c2 + q2;
    }

    // GEMM 2: arg += alpha @ Ws^T
    gemm_mma(acc, Xh, Xl, g_WsF, wm, wn, lane, true);
#pragma unroll
    for (int mt = 0; mt < 2; mt++)
#pragma unroll
        for (int nt = 0; nt < 4; nt++) {
            int row = wm * 32 + mt * 16 + g;
            int col = wn * 32 + nt * 8 + tq * 2;
            float2* p0 = (float2*)(g_arg + rb + (size_t)row * 256 + col);
            float2 v0 = *p0; v0.x += acc[mt][nt][0]; v0.y += acc[mt][nt][1]; *p0 = v0;
            float2* p1 = (float2*)(g_arg + rb + (size_t)(row + 8) * 256 + col);
            float2 v1 = *p1; v1.x += acc[mt][nt][2]; v1.y += acc[mt][nt][3]; *p1 = v1;
        }
}

// ---------------- pred + XTP(t+1) (grid 32, 256 thr) --------------------------
__global__ void pred_kernel(float* __restrict__ out, const int* __restrict__ ids,
                            const float* __restrict__ emb, int t) {
    int b = blockIdx.x, tid = threadIdx.x;
    __shared__ __align__(16) float ch[512];
    __shared__ __align__(16) float cpsh[256];
    float cs = 0.0f, cps = 0.0f;
#pragma unroll
    for (int p = 0; p < 8; p++) {
        cs += g_cpart[(b * 8 + p) * 256 + tid];
        cps += g_cppart[(b * 8 + p) * 256 + tid];
    }
    cpsh[tid] = cps;
    ch[tid] = cs;
    ch[256 + tid] = g_h[b * Dd + tid];
    __syncthreads();
    if (tid < 128) {
        int tn = (t + 1) & 31;
        int row = ids[b * Tt + tn] * 256;
        g_XTP[tid * 32 + b]         = pack2(emb[row + 2 * tid], emb[row + 2 * tid + 1]);
        g_XTP[(128 + tid) * 32 + b] = pack2(cpsh[2 * tid], cpsh[2 * tid + 1]);
        g_XTP[(256 + tid) * 32 + b] = pack2(ch[256 + 2 * tid], ch[256 + 2 * tid + 1]);
    }
    ull acc = 0ULL;
#pragma unroll 8
    for (int jp = 0; jp < 256; jp++) {
        ull x = *(const ull*)(ch + 2 * jp);
        asm("fma.rn.f32x2 %0,%1,%2,%0;" : "+l"(acc) : "l"(x), "l"(g_WgP[jp * 256 + tid]));
    }
    out[((size_t)b * Tt + t) * Dd + tid] = red2(acc);
}

// ---------------- launch --------------------------------------------------------
extern "C" void kernel_launch(void* const* d_in, const int* in_sizes, int n_in,
                              void* d_out, int out_size) {
    (void)in_sizes; (void)n_in; (void)out_size;
    const float* f    = (const float*)d_in[0];
    const int*   ids  = (const int*)d_in[1];
    const float* emb  = (const float*)d_in[2];
    const float* w_e  = (const float*)d_in[3];
    const float* w_h  = (const float*)d_in[4];
    const float* w_f  = (const float*)d_in[5];
    const float* w_q  = (const float*)d_in[6];
    const float* w_s  = (const float*)d_in[7];
    const float* w_g  = (const float*)d_in[8];
    const float* w_ih = (const float*)d_in[9];
    const float* w_hh = (const float*)d_in[10];
    float* out = (float*)d_out;

    cudaFuncSetAttribute(base_kernel, cudaFuncAttributeMaxDynamicSharedMemorySize, ATT_SMEM);
    cudaFuncSetAttribute(attn_kernel, cudaFuncAttributeMaxDynamicSharedMemorySize, ATT_SMEM);
    cudaFuncSetAttribute(gates_kernel, cudaFuncAttributeMaxDynamicSharedMemorySize, GSMEM);

    setup_a<<<2800, 256>>>(w_f, w_q, w_h, w_ih, w_hh, w_g, w_e, w_s, ids, emb);
    base_kernel<<<256, 512, ATT_SMEM>>>(f);
    for (int t = 0; t < Tt; t++) {
        gates_kernel<<<32, 256, GSMEM>>>();
        hw_kernel<<<32, 256>>>();
        attn_kernel<<<256, 512, ATT_SMEM>>>(f);
        pred_kernel<<<32, 256>>>(out, ids, emb, t);
    }
}

// round 15
// speedup vs baseline: 1.3426x; 1.3426x over previous
#include <cuda_runtime.h>
#include <cuda_bf16.h>
#include <math.h>

#define Dd 256
#define Bb 32
#define Ff 512
#define Tt 32

typedef unsigned long long ull;

// ---------------- scratch -----------------------------------------------------
__device__ float g_pe[Ff * Dd];
__device__ float g_arg[Bb * Ff * Dd];          // base + accumulated s@Ws^T
__device__ ull   g_WhP[128 * 256];
__device__ ull   g_wcombP[384 * 1024];         // [jp][gcol]
__device__ ull   g_WgP[256 * 256];
// HMMA B-fragment packs: [ks][ntile][lane] uint4 = {hi k0 pair, hi k0+8 pair, lo..., lo...}
__device__ uint4 g_WeF[16384];
__device__ uint4 g_WsF[16384];
__device__ uint4 g_WfF[16384];
__device__ uint4 g_WqF[16384];
__device__ float g_h[Bb * Dd], g_cell[Bb * Dd], g_cp[Bb * Dd], g_hw[Bb * Dd];
__device__ float g_cpart[256 * 256], g_cppart[256 * 256];

__device__ __forceinline__ float sigm(float x) { return 1.0f / (1.0f + expf(-x)); }
__device__ __forceinline__ ull pack2(float a, float b) {
    ull r; asm("mov.b64 %0, {%1, %2};" : "=l"(r) : "f"(a), "f"(b)); return r;
}
__device__ __forceinline__ float red2(ull a) {
    return __uint_as_float((unsigned)a) + __uint_as_float((unsigned)(a >> 32));
}
__device__ __forceinline__ unsigned pkbf(float a, float b) {
    __nv_bfloat16 ha = __float2bfloat16(a), hb = __float2bfloat16(b);
    return (unsigned)__bfloat16_as_ushort(ha) | ((unsigned)__bfloat16_as_ushort(hb) << 16);
}

#define MMA(d, a, b0, b1) \
    asm("mma.sync.aligned.m16n8k16.row.col.f32.bf16.bf16.f32 " \
        "{%0,%1,%2,%3},{%4,%5,%6,%7},{%8,%9},{%0,%1,%2,%3};" \
        : "+f"((d)[0]), "+f"((d)[1]), "+f"((d)[2]), "+f"((d)[3]) \
        : "r"((a)[0]), "r"((a)[1]), "r"((a)[2]), "r"((a)[3]), "r"(b0), "r"(b1))

// ---------------- mega-setup ---------------------------------------------------
__global__ void setup_a(const float* __restrict__ w_f, const float* __restrict__ w_q,
                        const float* __restrict__ w_h, const float* __restrict__ w_ih,
                        const float* __restrict__ w_hh, const float* __restrict__ w_g,
                        const float* __restrict__ w_e, const float* __restrict__ w_s) {
    int bb = blockIdx.x, tid = threadIdx.x;
    if (bb < 512) {
        int idx = bb * 256 + tid;
        int pos = idx >> 8, d = idx & 255;
        float expo = (float)(d & ~1) / (float)Dd;
        float ang = (float)pos / powf(10000.0f, expo);
        double a = (double)ang;
        g_pe[idx] = (d & 1) ? (float)cos(a) : (float)sin(a);
    } else if (bb < 640) {
        int idx = (bb - 512) * 256 + tid;
        int k = idx >> 8, o = idx & 255;
        g_WhP[idx] = pack2(w_h[o * 256 + 2 * k], w_h[o * 256 + 2 * k + 1]);
    } else if (bb < 2176) {
        int idx = (bb - 640) * 256 + tid;
        int jp = idx >> 10, gcol = idx & 1023;
        float a, b;
        if (jp < 256) { a = w_ih[gcol * 512 + 2 * jp]; b = w_ih[gcol * 512 + 2 * jp + 1]; }
        else { int j2 = jp - 256; a = w_hh[gcol * 256 + 2 * j2]; b = w_hh[gcol * 256 + 2 * j2 + 1]; }
        g_wcombP[idx] = pack2(a, b);
    } else if (bb < 2432) {
        int idx = (bb - 2176) * 256 + tid;
        int jp = idx >> 8, o = idx & 255;
        g_WgP[idx] = pack2(w_g[o * 512 + 2 * jp], w_g[o * 512 + 2 * jp + 1]);
    } else if (bb < 2688) {
        int idx = (bb - 2432) * 256 + tid;          // 0..65535
        int sel = idx >> 14;
        const float* W = (sel == 0) ? w_e : (sel == 1) ? w_s : (sel == 2) ? w_f : w_q;
        uint4* dst = (sel == 0) ? g_WeF : (sel == 1) ? g_WsF : (sel == 2) ? g_WfF : g_WqF;
        int e = idx & 16383;
        int ks = e >> 10, ntg = (e >> 5) & 31, ln = e & 31;
        int n = ntg * 8 + (ln >> 2);
        int k0 = ks * 16 + (ln & 3) * 2;
        float w00 = W[n * 256 + k0],     w01 = W[n * 256 + k0 + 1];
        float w80 = W[n * 256 + k0 + 8], w81 = W[n * 256 + k0 + 9];
        __nv_bfloat16 h00 = __float2bfloat16(w00), h01 = __float2bfloat16(w01);
        __nv_bfloat16 h80 = __float2bfloat16(w80), h81 = __float2bfloat16(w81);
        uint4 v;
        v.x = (unsigned)__bfloat16_as_ushort(h00) | ((unsigned)__bfloat16_as_ushort(h01) << 16);
        v.y = (unsigned)__bfloat16_as_ushort(h80) | ((unsigned)__bfloat16_as_ushort(h81) << 16);
        v.z = pkbf(w00 - __bfloat162float(h00), w01 - __bfloat162float(h01));
        v.w = pkbf(w80 - __bfloat162float(h80), w81 - __bfloat162float(h81));
        dst[e] = v;
    } else {
        int idx = (bb - 2688) * 256 + tid;          // 24576: zero h, cell, cp
        if (idx < 8192) g_h[idx] = 0.0f;
        else if (idx < 16384) g_cell[idx - 8192] = 0.0f;
        else g_cp[idx - 16384] = 0.0f;
    }
}

// ---------------- HMMA split-bf16 GEMM core ------------------------------------
__device__ __forceinline__ void gemm_mma(float acc[2][4][4],
                                         const __nv_bfloat16* Xh, const __nv_bfloat16* Xl,
                                         const uint4* __restrict__ WF,
                                         int wm, int wn, int lane, bool zero) {
    int g = lane >> 2, tq = lane & 3;
    if (zero) {
#pragma unroll
        for (int mt = 0; mt < 2; mt++)
#pragma unroll
            for (int nt = 0; nt < 4; nt++)
#pragma unroll
                for (int i = 0; i < 4; i++) acc[mt][nt][i] = 0.0f;
    }
#pragma unroll 2
    for (int ks = 0; ks < 16; ks++) {
        uint4 bf[4];
#pragma unroll
        for (int nt = 0; nt < 4; nt++)
            bf[nt] = WF[((ks * 32 + wn * 4 + nt) * 32) + lane];
        unsigned ah[2][4], al[2][4];
        int k0 = ks * 16 + tq * 2;
#pragma unroll
        for (int mt = 0; mt < 2; mt++) {
            int r0 = wm * 32 + mt * 16 + g;
            ah[mt][0] = *(const unsigned*)(Xh + r0 * 264 + k0);
            ah[mt][1] = *(const unsigned*)(Xh + (r0 + 8) * 264 + k0);
            ah[mt][2] = *(const unsigned*)(Xh + r0 * 264 + k0 + 8);
            ah[mt][3] = *(const unsigned*)(Xh + (r0 + 8) * 264 + k0 + 8);
            al[mt][0] = *(const unsigned*)(Xl + r0 * 264 + k0);
            al[mt][1] = *(const unsigned*)(Xl + (r0 + 8) * 264 + k0);
            al[mt][2] = *(const unsigned*)(Xl + r0 * 264 + k0 + 8);
            al[mt][3] = *(const unsigned*)(Xl + (r0 + 8) * 264 + k0 + 8);
        }
#pragma unroll
        for (int nt = 0; nt < 4; nt++)
#pragma unroll
            for (int mt = 0; mt < 2; mt++) {
                MMA(acc[mt][nt], ah[mt], bf[nt].x, bf[nt].y);
                MMA(acc[mt][nt], ah[mt], bf[nt].z, bf[nt].w);
                MMA(acc[mt][nt], al[mt], bf[nt].x, bf[nt].y);
            }
    }
}

// smem byte offsets (dynamic smem, attn/base)
#define XH_OFF 0
#define XL_OFF 33792
#define RS_OFF 67584
#define RT_OFF 69632
#define PC_OFF 69888
#define PQ_OFF 71936
#define ATT_SMEM 73984

// ---------------- base: arg = f @ Wf^T + pe @ Wq^T (HMMA) ----------------------
__global__ void __launch_bounds__(512, 1) base_kernel(const float* __restrict__ f) {
    extern __shared__ __align__(16) unsigned char smem[];
    __nv_bfloat16* Xh = (__nv_bfloat16*)(smem + XH_OFF);
    __nv_bfloat16* Xl = (__nv_bfloat16*)(smem + XL_OFF);
    int tid = threadIdx.x;
    int tile = blockIdx.x;
    int b = tile >> 3, f0 = (tile & 7) * 64;
    size_t rb = ((size_t)b * Ff + f0) * Dd;
    int lane = tid & 31, wid = tid >> 5;
    int wm = wid & 1, wn = wid >> 1;
    int g = lane >> 2, tq = lane & 3;
    float acc[2][4][4];

    {
        int c = tid & 255, hf = tid >> 8;
#pragma unroll 4
        for (int r = 0; r < 32; r++) {
            int row = hf * 32 + r;
            float x = g_pe[(size_t)(f0 + row) * 256 + c];
            __nv_bfloat16 h = __float2bfloat16(x);
            Xh[row * 264 + c] = h;
            Xl[row * 264 + c] = __float2bfloat16(x - __bfloat162float(h));
        }
    }
    __syncthreads();
    gemm_mma(acc, Xh, Xl, g_WqF, wm, wn, lane, true);
    __syncthreads();

    {
        int c = tid & 255, hf = tid >> 8;
#pragma unroll 4
        for (int r = 0; r < 32; r++) {
            int row = hf * 32 + r;
            float x = f[rb + (size_t)row * 256 + c];
            __nv_bfloat16 h = __float2bfloat16(x);
            Xh[row * 264 + c] = h;
            Xl[row * 264 + c] = __float2bfloat16(x - __bfloat162float(h));
        }
    }
    __syncthreads();
    gemm_mma(acc, Xh, Xl, g_WfF, wm, wn, lane, false);

#pragma unroll
    for (int mt = 0; mt < 2; mt++)
#pragma unroll
        for (int nt = 0; nt < 4; nt++) {
            int row = wm * 32 + mt * 16 + g;
            int col = wn * 32 + nt * 8 + tq * 2;
            *(float2*)(g_arg + rb + (size_t)row * 256 + col) =
                make_float2(acc[mt][nt][0], acc[mt][nt][1]);
            *(float2*)(g_arg + rb + (size_t)(row + 8) * 256 + col) =
                make_float2(acc[mt][nt][2], acc[mt][nt][3]);
        }
}

// ---------------- fused LSTM step: gates + cell/h + hw (grid 32, 1024 thr) -----
__global__ void lstm_step_kernel(const int* __restrict__ ids,
                                 const float* __restrict__ emb, int t) {
    int b = blockIdx.x, tid = threadIdx.x;
    __shared__ __align__(16) float buf[768];
    __shared__ __align__(16) float hbuf[256];
    __shared__ float gsh[1024];
    if (tid < 256)      buf[tid] = emb[ids[b * Tt + t] * Dd + tid];
    else if (tid < 512) buf[tid] = g_cp[b * Dd + (tid - 256)];
    else if (tid < 768) buf[tid] = g_h[b * Dd + (tid - 512)];
    __syncthreads();
    ull acc = 0ULL;
#pragma unroll 8
    for (int jp = 0; jp < 384; jp++) {
        ull x = *(const ull*)(buf + 2 * jp);
        asm("fma.rn.f32x2 %0,%1,%2,%0;" : "+l"(acc) : "l"(x), "l"(g_wcombP[jp * 1024 + tid]));
    }
    gsh[tid] = red2(acc);
    __syncthreads();
    if (tid < 256) {
        float gi = gsh[tid], gf = gsh[256 + tid], gg = gsh[512 + tid], go = gsh[768 + tid];
        float c = sigm(gf) * g_cell[b * Dd + tid] + sigm(gi) * tanhf(gg);
        float hn = sigm(go) * tanhf(c);
        g_cell[b * Dd + tid] = c;
        g_h[b * Dd + tid] = hn;
        hbuf[tid] = hn;
    }
    __syncthreads();
    if (tid < 256) {
        ull a2 = 0ULL;
#pragma unroll 8
        for (int jp = 0; jp < 128; jp++) {
            ull x = *(const ull*)(hbuf + 2 * jp);
            asm("fma.rn.f32x2 %0,%1,%2,%0;" : "+l"(a2) : "l"(x), "l"(g_WhP[jp * 256 + tid]));
        }
        g_hw[b * Dd + tid] = red2(a2);
    }
}

// ---------------- HMMA attention step (grid 256, 512 thr) ---------------------
__global__ void __launch_bounds__(512, 1) attn_kernel(const float* __restrict__ f) {
    extern __shared__ __align__(16) unsigned char smem[];
    __nv_bfloat16* Xh = (__nv_bfloat16*)(smem + XH_OFF);
    __nv_bfloat16* Xl = (__nv_bfloat16*)(smem + XL_OFF);
    float* rs = (float*)(smem + RS_OFF);
    float* rt = (float*)(smem + RT_OFF);
    float* pc = (float*)(smem + PC_OFF);
    float* pq = (float*)(smem + PQ_OFF);
    int tid = threadIdx.x;
    int tile = blockIdx.x;
    int b = tile >> 3, f0 = (tile & 7) * 64;
    size_t rb = ((size_t)b * Ff + f0) * Dd;

    // phase 1: X = tanh(hw + arg) -> bf16 hi/lo planes
    {
        int c = tid & 255, hf = tid >> 8;
        float hwv = g_hw[b * Dd + c];
#pragma unroll 4
        for (int r = 0; r < 32; r++) {
            int row = hf * 32 + r;
            float x = tanhf(hwv + g_arg[rb + (size_t)row * 256 + c]);
            __nv_bfloat16 h = __float2bfloat16(x);
            Xh[row * 264 + c] = h;
            Xl[row * 264 + c] = __float2bfloat16(x - __bfloat162float(h));
        }
    }
    __syncthreads();

    int lane = tid & 31, wid = tid >> 5;
    int wm = wid & 1, wn = wid >> 1;
    int g = lane >> 2, tq = lane & 3;

    float acc[2][4][4];
    gemm_mma(acc, Xh, Xl, g_WeF, wm, wn, lane, true);

    // softmax (tanh-bounded energies; no max pass)
    {
        float p0[2], p1[2];
#pragma unroll
        for (int mt = 0; mt < 2; mt++) {
            p0[mt] = 0.0f; p1[mt] = 0.0f;
#pragma unroll
            for (int nt = 0; nt < 4; nt++) {
                acc[mt][nt][0] = __expf(acc[mt][nt][0]);
                acc[mt][nt][1] = __expf(acc[mt][nt][1]);
                acc[mt][nt][2] = __expf(acc[mt][nt][2]);
                acc[mt][nt][3] = __expf(acc[mt][nt][3]);
                p0[mt] += acc[mt][nt][0] + acc[mt][nt][1];
                p1[mt] += acc[mt][nt][2] + acc[mt][nt][3];
            }
#pragma unroll
            for (int o = 1; o <= 2; o <<= 1) {
                p0[mt] += __shfl_xor_sync(0xffffffffu, p0[mt], o);
                p1[mt] += __shfl_xor_sync(0xffffffffu, p1[mt], o);
            }
        }
        if (tq == 0) {
#pragma unroll
            for (int mt = 0; mt < 2; mt++) {
                rs[wn * 64 + wm * 32 + mt * 16 + g] = p0[mt];
                rs[wn * 64 + wm * 32 + mt * 16 + g + 8] = p1[mt];
            }
        }
        __syncthreads();
        if (tid < 64) {
            float s = 0.0f;
#pragma unroll
            for (int w = 0; w < 8; w++) s += rs[w * 64 + tid];
            rt[tid] = 1.0f / s;
        }
        __syncthreads();
#pragma unroll
        for (int mt = 0; mt < 2; mt++) {
            float i0 = rt[wm * 32 + mt * 16 + g];
            float i1 = rt[wm * 32 + mt * 16 + g + 8];
#pragma unroll
            for (int nt = 0; nt < 4; nt++) {
                float a0 = acc[mt][nt][0] * i0, a1 = acc[mt][nt][1] * i0;
                float a2 = acc[mt][nt][2] * i1, a3 = acc[mt][nt][3] * i1;
                int row = wm * 32 + mt * 16 + g;
                int col = wn * 32 + nt * 8 + tq * 2;
                __nv_bfloat16 h0 = __float2bfloat16(a0), h1 = __float2bfloat16(a1);
                __nv_bfloat16 h2 = __float2bfloat16(a2), h3 = __float2bfloat16(a3);
                *(unsigned*)(Xh + row * 264 + col) =
                    (unsigned)__bfloat16_as_ushort(h0) | ((unsigned)__bfloat16_as_ushort(h1) << 16);
                *(unsigned*)(Xl + row * 264 + col) =
                    pkbf(a0 - __bfloat162float(h0), a1 - __bfloat162float(h1));
                *(unsigned*)(Xh + (row + 8) * 264 + col) =
                    (unsigned)__bfloat16_as_ushort(h2) | ((unsigned)__bfloat16_as_ushort(h3) << 16);
                *(unsigned*)(Xl + (row + 8) * 264 + col) =
                    pkbf(a2 - __bfloat162float(h2), a3 - __bfloat162float(h3));
            }
        }
    }
    __syncthreads();

    // c / cp partial reductions
    {
        int c = tid & 255, hf = tid >> 8;
        float ca = 0.0f, qa = 0.0f;
        const float* fp = f + rb + (size_t)(hf * 32) * 256 + c;
        const float* pp = g_pe + (size_t)(f0 + hf * 32) * 256 + c;
#pragma unroll 4
        for (int r = 0; r < 32; r++) {
            int row = hf * 32 + r;
            float a = __bfloat162float(Xh[row * 264 + c]) + __bfloat162float(Xl[row * 264 + c]);
            ca += a * fp[r * 256];
            qa += a * pp[r * 256];
        }
        pc[hf * 256 + c] = ca;
        pq[hf * 256 + c] = qa;
    }
    __syncthreads();
    if (tid < 256) {
        float c2 = pc[tid] + pc[256 + tid];
        float q2 = pq[tid] + pq[256 + tid];
        g_cpart[tile * 256 + tid] = c2;
        g_cppart[tile * 256 + tid] = c2 + q2;
    }

    // GEMM 2: arg += alpha @ Ws^T
    gemm_mma(acc, Xh, Xl, g_WsF, wm, wn, lane, true);
#pragma unroll
    for (int mt = 0; mt < 2; mt++)
#pragma unroll
        for (int nt = 0; nt < 4; nt++) {
            int row = wm * 32 + mt * 16 + g;
            int col = wn * 32 + nt * 8 + tq * 2;
            float2* p0 = (float2*)(g_arg + rb + (size_t)row * 256 + col);
            float2 v0 = *p0; v0.x += acc[mt][nt][0]; v0.y += acc[mt][nt][1]; *p0 = v0;
            float2* p1 = (float2*)(g_arg + rb + (size_t)(row + 8) * 256 + col);
            float2 v1 = *p1; v1.x += acc[mt][nt][2]; v1.y += acc[mt][nt][3]; *p1 = v1;
        }
}

// ---------------- pred (grid 32, 256 thr) -------------------------------------
__global__ void pred_kernel(float* __restrict__ out, int t) {
    int b = blockIdx.x, tid = threadIdx.x;
    __shared__ __align__(16) float ch[512];
    float cs = 0.0f, cps = 0.0f;
#pragma unroll
    for (int p = 0; p < 8; p++) {
        cs += g_cpart[(b * 8 + p) * 256 + tid];
        cps += g_cppart[(b * 8 + p) * 256 + tid];
    }
    g_cp[b * Dd + tid] = cps;
    ch[tid] = cs;
    ch[256 + tid] = g_h[b * Dd + tid];
    __syncthreads();
    ull acc = 0ULL;
#pragma unroll 8
    for (int jp = 0; jp < 256; jp++) {
        ull x = *(const ull*)(ch + 2 * jp);
        asm("fma.rn.f32x2 %0,%1,%2,%0;" : "+l"(acc) : "l"(x), "l"(g_WgP[jp * 256 + tid]));
    }
    out[((size_t)b * Tt + t) * Dd + tid] = red2(acc);
}

// ---------------- launch --------------------------------------------------------
extern "C" void kernel_launch(void* const* d_in, const int* in_sizes, int n_in,
                              void* d_out, int out_size) {
    (void)in_sizes; (void)n_in; (void)out_size;
    const float* f    = (const float*)d_in[0];
    const int*   ids  = (const int*)d_in[1];
    const float* emb  = (const float*)d_in[2];
    const float* w_e  = (const float*)d_in[3];
    const float* w_h  = (const float*)d_in[4];
    const float* w_f  = (const float*)d_in[5];
    const float* w_q  = (const float*)d_in[6];
    const float* w_s  = (const float*)d_in[7];
    const float* w_g  = (const float*)d_in[8];
    const float* w_ih = (const float*)d_in[9];
    const float* w_hh = (const float*)d_in[10];
    float* out = (float*)d_out;

    cudaFuncSetAttribute(base_kernel, cudaFuncAttributeMaxDynamicSharedMemorySize, ATT_SMEM);
    cudaFuncSetAttribute(attn_kernel, cudaFuncAttributeMaxDynamicSharedMemorySize, ATT_SMEM);

    setup_a<<<2784, 256>>>(w_f, w_q, w_h, w_ih, w_hh, w_g, w_e, w_s);   // global #2
    base_kernel<<<256, 512, ATT_SMEM>>>(f);                              // global #3
    for (int t = 0; t < Tt; t++) {
        lstm_step_kernel<<<32, 1024>>>(ids, emb, t);                     // #4 (t=0)
        attn_kernel<<<256, 512, ATT_SMEM>>>(f);                          // #5 (t=0) <- profiled
        pred_kernel<<<32, 256>>>(out, t);
    }
}